// round 1
// baseline (speedup 1.0000x reference)
#include <cuda_runtime.h>
#include <cuda_bf16.h>
#include <math.h>

// Problem constants
#define NSEQ   2048
#define DIM    2048
#define NHEAD  32
#define KVH    4
#define REP    8          // NHEAD / KVH
#define HD     64         // head dim
#define KV_DIM 256        // KVH * HD
#define SCALE  0.125f     // 1/sqrt(64)

// Scratch (device globals — no allocation allowed)
__device__ float g_Q[NSEQ * DIM];     // 16 MB
__device__ float g_K[NSEQ * KV_DIM];  // 2 MB
__device__ float g_V[NSEQ * KV_DIM];  // 2 MB
__device__ float g_Y[NSEQ * DIM];     // 16 MB

// ---------------------------------------------------------------------------
// SGEMM: C[M, Nc] = A[M, K] * B[Nc, K]^T   (both A and B are K-major, row-major)
// 64x64 tile, 16x16 threads, 4x4 micro-tile per thread, K-tiles of 16.
// ---------------------------------------------------------------------------
#define TS 64
#define KT 16

__global__ __launch_bounds__(256) void sgemm_nt(
    const float* __restrict__ A, const float* __restrict__ B,
    float* __restrict__ C, int M, int Nc, int K)
{
    __shared__ float As[TS][KT + 1];
    __shared__ float Bs[TS][KT + 1];

    const int tx = threadIdx.x;   // 0..15
    const int ty = threadIdx.y;   // 0..15
    const int t  = ty * 16 + tx;

    const int row0 = blockIdx.y * TS;
    const int col0 = blockIdx.x * TS;

    // Each thread loads one float4 of A and one of B per K-tile.
    const int lr = t >> 2;          // 0..63
    const int lc = (t & 3) * 4;     // 0,4,8,12

    float acc[4][4];
    #pragma unroll
    for (int i = 0; i < 4; ++i)
        #pragma unroll
        for (int j = 0; j < 4; ++j) acc[i][j] = 0.f;

    for (int k0 = 0; k0 < K; k0 += KT) {
        float4 a4 = *(const float4*)(A + (size_t)(row0 + lr) * K + k0 + lc);
        float4 b4 = *(const float4*)(B + (size_t)(col0 + lr) * K + k0 + lc);
        As[lr][lc + 0] = a4.x; As[lr][lc + 1] = a4.y;
        As[lr][lc + 2] = a4.z; As[lr][lc + 3] = a4.w;
        Bs[lr][lc + 0] = b4.x; Bs[lr][lc + 1] = b4.y;
        Bs[lr][lc + 2] = b4.z; Bs[lr][lc + 3] = b4.w;
        __syncthreads();

        #pragma unroll
        for (int kk = 0; kk < KT; ++kk) {
            float a[4], b[4];
            #pragma unroll
            for (int i = 0; i < 4; ++i) a[i] = As[ty * 4 + i][kk];
            #pragma unroll
            for (int j = 0; j < 4; ++j) b[j] = Bs[tx * 4 + j][kk];
            #pragma unroll
            for (int i = 0; i < 4; ++i)
                #pragma unroll
                for (int j = 0; j < 4; ++j)
                    acc[i][j] = fmaf(a[i], b[j], acc[i][j]);
        }
        __syncthreads();
    }

    #pragma unroll
    for (int i = 0; i < 4; ++i) {
        float4 out4 = make_float4(acc[i][0], acc[i][1], acc[i][2], acc[i][3]);
        *(float4*)(C + (size_t)(row0 + ty * 4 + i) * Nc + col0 + tx * 4) = out4;
    }
}

// ---------------------------------------------------------------------------
// RoPE applied in-place to Q [N, H, 64] and K [N, KVH, 64].
// cos/sin are [N, 64] with cos[:, d] == cos[:, d+32].
// ---------------------------------------------------------------------------
__global__ __launch_bounds__(256) void rope_kernel(
    const float* __restrict__ cosT, const float* __restrict__ sinT)
{
    const int QP = NSEQ * NHEAD * 32;   // pairs in Q
    const int KP = NSEQ * KVH * 32;     // pairs in K
    int idx = blockIdx.x * blockDim.x + threadIdx.x;
    if (idx >= QP + KP) return;

    float* base;
    int n, d;
    if (idx < QP) {
        n = idx / (NHEAD * 32);
        int rem = idx % (NHEAD * 32);
        int h = rem >> 5;
        d = rem & 31;
        base = g_Q + (size_t)n * DIM + h * HD;
    } else {
        int k = idx - QP;
        n = k / (KVH * 32);
        int rem = k % (KVH * 32);
        int h = rem >> 5;
        d = rem & 31;
        base = g_K + (size_t)n * KV_DIM + h * HD;
    }
    float c = cosT[n * HD + d];
    float s = sinT[n * HD + d];
    float x0 = base[d];
    float x1 = base[d + 32];
    base[d]      = x0 * c - x1 * s;
    base[d + 32] = x1 * c + x0 * s;
}

// ---------------------------------------------------------------------------
// Flash attention, causal, GQA. One block per (head, 64-row query tile).
// 16x16 threads; each thread owns a 4x4 tile of the 64x64 S / 64x64 O.
// ---------------------------------------------------------------------------
#define PADW 65

__global__ __launch_bounds__(256) void attn_kernel(float* __restrict__ Y)
{
    extern __shared__ float sm[];
    float* Qs   = sm;                    // 64*65
    float* Ks   = Qs + 64 * PADW;        // 64*65
    float* Vs   = Ks + 64 * PADW;        // 64*65
    float* Ps   = Vs + 64 * PADW;        // 64*65
    float* mrow = Ps + 64 * PADW;        // 64
    float* lrow = mrow + 64;             // 64
    float* arow = lrow + 64;             // 64

    const int h  = blockIdx.x;
    const int q0 = blockIdx.y * 64;
    const int kh = h / REP;

    const int tx = threadIdx.x, ty = threadIdx.y;
    const int t  = ty * 16 + tx;

    // Load Q tile (64 rows x 64 cols) as float4
    for (int it = t; it < 64 * 16; it += 256) {
        int r  = it >> 4;
        int c4 = (it & 15) * 4;
        float4 v4 = *(const float4*)(g_Q + (size_t)(q0 + r) * DIM + h * HD + c4);
        Qs[r * PADW + c4 + 0] = v4.x; Qs[r * PADW + c4 + 1] = v4.y;
        Qs[r * PADW + c4 + 2] = v4.z; Qs[r * PADW + c4 + 3] = v4.w;
    }
    if (t < 64) { mrow[t] = -1e30f; lrow[t] = 0.f; }

    float O[4][4];
    #pragma unroll
    for (int i = 0; i < 4; ++i)
        #pragma unroll
        for (int j = 0; j < 4; ++j) O[i][j] = 0.f;

    __syncthreads();

    for (int k0 = 0; k0 <= q0; k0 += 64) {
        // Load K and V tiles
        for (int it = t; it < 64 * 16; it += 256) {
            int r  = it >> 4;
            int c4 = (it & 15) * 4;
            const float* kp = g_K + (size_t)(k0 + r) * KV_DIM + kh * HD + c4;
            const float* vp = g_V + (size_t)(k0 + r) * KV_DIM + kh * HD + c4;
            float4 k4 = *(const float4*)kp;
            float4 v4 = *(const float4*)vp;
            Ks[r * PADW + c4 + 0] = k4.x; Ks[r * PADW + c4 + 1] = k4.y;
            Ks[r * PADW + c4 + 2] = k4.z; Ks[r * PADW + c4 + 3] = k4.w;
            Vs[r * PADW + c4 + 0] = v4.x; Vs[r * PADW + c4 + 1] = v4.y;
            Vs[r * PADW + c4 + 2] = v4.z; Vs[r * PADW + c4 + 3] = v4.w;
        }
        __syncthreads();

        // S = Q @ K^T (64x64x64)
        float sacc[4][4];
        #pragma unroll
        for (int i = 0; i < 4; ++i)
            #pragma unroll
            for (int j = 0; j < 4; ++j) sacc[i][j] = 0.f;

        #pragma unroll 8
        for (int d = 0; d < HD; ++d) {
            float a[4], b[4];
            #pragma unroll
            for (int i = 0; i < 4; ++i) a[i] = Qs[(ty * 4 + i) * PADW + d];
            #pragma unroll
            for (int j = 0; j < 4; ++j) b[j] = Ks[(tx * 4 + j) * PADW + d];
            #pragma unroll
            for (int i = 0; i < 4; ++i)
                #pragma unroll
                for (int j = 0; j < 4; ++j)
                    sacc[i][j] = fmaf(a[i], b[j], sacc[i][j]);
        }

        const bool diag = (k0 == q0);
        #pragma unroll
        for (int i = 0; i < 4; ++i)
            #pragma unroll
            for (int j = 0; j < 4; ++j) {
                float sv = sacc[i][j] * SCALE;
                if (diag && (tx * 4 + j) > (ty * 4 + i)) sv = -1e30f;
                Ps[(ty * 4 + i) * PADW + tx * 4 + j] = sv;
            }
        __syncthreads();

        // Online softmax row update (64 threads, one per row; pad=65 -> conflict free)
        if (t < 64) {
            float m_old = mrow[t];
            float mx = m_old;
            #pragma unroll 8
            for (int s = 0; s < 64; ++s) mx = fmaxf(mx, Ps[t * PADW + s]);
            float sum = 0.f;
            #pragma unroll 8
            for (int s = 0; s < 64; ++s) {
                float p = __expf(Ps[t * PADW + s] - mx);
                Ps[t * PADW + s] = p;
                sum += p;
            }
            float alpha = __expf(m_old - mx);
            mrow[t] = mx;
            lrow[t] = lrow[t] * alpha + sum;
            arow[t] = alpha;
        }
        __syncthreads();

        // Rescale O and accumulate P @ V
        float al[4];
        #pragma unroll
        for (int i = 0; i < 4; ++i) al[i] = arow[ty * 4 + i];
        #pragma unroll
        for (int i = 0; i < 4; ++i)
            #pragma unroll
            for (int j = 0; j < 4; ++j) O[i][j] *= al[i];

        #pragma unroll 8
        for (int s = 0; s < 64; ++s) {
            float p[4], vv[4];
            #pragma unroll
            for (int i = 0; i < 4; ++i) p[i] = Ps[(ty * 4 + i) * PADW + s];
            #pragma unroll
            for (int j = 0; j < 4; ++j) vv[j] = Vs[s * PADW + tx * 4 + j];
            #pragma unroll
            for (int i = 0; i < 4; ++i)
                #pragma unroll
                for (int j = 0; j < 4; ++j)
                    O[i][j] = fmaf(p[i], vv[j], O[i][j]);
        }
        __syncthreads();
    }

    // Normalize and write y[n, h*64 + c]
    #pragma unroll
    for (int i = 0; i < 4; ++i) {
        float inv = 1.f / lrow[ty * 4 + i];
        float4 out4 = make_float4(O[i][0] * inv, O[i][1] * inv,
                                  O[i][2] * inv, O[i][3] * inv);
        *(float4*)(Y + (size_t)(q0 + ty * 4 + i) * DIM + h * HD + tx * 4) = out4;
    }
}

// ---------------------------------------------------------------------------
// Launch
// ---------------------------------------------------------------------------
extern "C" void kernel_launch(void* const* d_in, const int* in_sizes, int n_in,
                              void* d_out, int out_size)
{
    const float* x    = (const float*)d_in[0];
    const float* Wq   = (const float*)d_in[1];
    const float* Wk   = (const float*)d_in[2];
    const float* Wv   = (const float*)d_in[3];
    const float* Wo   = (const float*)d_in[4];
    const float* cosT = (const float*)d_in[5];
    const float* sinT = (const float*)d_in[6];
    float* out = (float*)d_out;

    float *dQ, *dK, *dV, *dY;
    cudaGetSymbolAddress((void**)&dQ, g_Q);
    cudaGetSymbolAddress((void**)&dK, g_K);
    cudaGetSymbolAddress((void**)&dV, g_V);
    cudaGetSymbolAddress((void**)&dY, g_Y);

    dim3 blk(16, 16);

    // QKV projections
    sgemm_nt<<<dim3(DIM / TS, NSEQ / TS), blk>>>(x, Wq, dQ, NSEQ, DIM, DIM);
    sgemm_nt<<<dim3(KV_DIM / TS, NSEQ / TS), blk>>>(x, Wk, dK, NSEQ, KV_DIM, DIM);
    sgemm_nt<<<dim3(KV_DIM / TS, NSEQ / TS), blk>>>(x, Wv, dV, NSEQ, KV_DIM, DIM);

    // RoPE on Q and K
    {
        int total = NSEQ * NHEAD * 32 + NSEQ * KVH * 32;
        rope_kernel<<<(total + 255) / 256, 256>>>(cosT, sinT);
    }

    // Attention
    {
        int smem = (4 * 64 * PADW + 3 * 64) * sizeof(float);   // ~67 KB
        cudaFuncSetAttribute(attn_kernel,
                             cudaFuncAttributeMaxDynamicSharedMemorySize, smem);
        attn_kernel<<<dim3(NHEAD, NSEQ / 64), blk, smem>>>(dY);
    }

    // Output projection
    sgemm_nt<<<dim3(DIM / TS, NSEQ / TS), blk>>>(dY, Wo, out, NSEQ, DIM, DIM);
}

// round 8
// speedup vs baseline: 2.7269x; 2.7269x over previous
#include <cuda_runtime.h>
#include <cuda_bf16.h>
#include <cstdint>
#include <math.h>

// Problem constants
#define NSEQ   2048
#define DIM    2048
#define NHEAD  32
#define KVH    4
#define REP    8
#define HD     64
#define KV_DIM 256
#define SCALE  0.125f

// Scratch
__device__ float g_Q[NSEQ * DIM];
__device__ float g_K[NSEQ * KV_DIM];
__device__ float g_V[NSEQ * KV_DIM];
__device__ float g_Y[NSEQ * DIM];

// Round fp32 -> tf32 (round-to-nearest) kept in a float container.
__device__ __forceinline__ float tf32r(float x) {
    unsigned int r;
    asm("cvt.rna.tf32.f32 %0, %1;" : "=r"(r) : "f"(x));
    return __uint_as_float(r);
}

// m16n8k8 tf32 mma, acc fp32
__device__ __forceinline__ void mma_tf32(float c[4], const float a[4], const float b[2]) {
    asm volatile(
        "mma.sync.aligned.m16n8k8.row.col.f32.tf32.tf32.f32 "
        "{%0,%1,%2,%3}, {%4,%5,%6,%7}, {%8,%9}, {%0,%1,%2,%3};\n"
        : "+f"(c[0]), "+f"(c[1]), "+f"(c[2]), "+f"(c[3])
        : "r"(__float_as_uint(a[0])), "r"(__float_as_uint(a[1])),
          "r"(__float_as_uint(a[2])), "r"(__float_as_uint(a[3])),
          "r"(__float_as_uint(b[0])), "r"(__float_as_uint(b[1])));
}

// ---------------------------------------------------------------------------
// GEMM: C[M,Nc] = A[M,K] * B[Nc,K]^T  via tf32 mma.sync.
// Block 128x128, BK=32, 8 warps (2x4), warp tile 64x32.
// ---------------------------------------------------------------------------
#define BK 32
#define APAD 36   // 36 % 32 == 4 -> (4g + tig) conflict-free fragment loads

__global__ __launch_bounds__(256) void gemm_tf32(
    const float* __restrict__ A, const float* __restrict__ B,
    float* __restrict__ C, int M, int Nc, int K)
{
    __shared__ float As[128 * APAD];
    __shared__ float Bs[128 * APAD];

    const int tid  = threadIdx.x;
    const int warp = tid >> 5, lane = tid & 31;
    const int g = lane >> 2, tig = lane & 3;
    const int wm = warp >> 2;       // 0..1
    const int wn = warp & 3;        // 0..3
    const int row0 = blockIdx.y * 128;
    const int col0 = blockIdx.x * 128;

    float acc[4][4][4];
    #pragma unroll
    for (int mt = 0; mt < 4; ++mt)
        #pragma unroll
        for (int nt = 0; nt < 4; ++nt)
            #pragma unroll
            for (int r = 0; r < 4; ++r) acc[mt][nt][r] = 0.f;

    for (int k0 = 0; k0 < K; k0 += BK) {
        // 128x32 tile = 1024 float4; 256 threads -> 4 each (A and B)
        #pragma unroll
        for (int f = tid; f < 1024; f += 256) {
            int r = f >> 3, c = (f & 7) * 4;
            float4 a4 = *(const float4*)(A + (size_t)(row0 + r) * K + k0 + c);
            float4 b4 = *(const float4*)(B + (size_t)(col0 + r) * K + k0 + c);
            As[r * APAD + c + 0] = tf32r(a4.x);
            As[r * APAD + c + 1] = tf32r(a4.y);
            As[r * APAD + c + 2] = tf32r(a4.z);
            As[r * APAD + c + 3] = tf32r(a4.w);
            Bs[r * APAD + c + 0] = tf32r(b4.x);
            Bs[r * APAD + c + 1] = tf32r(b4.y);
            Bs[r * APAD + c + 2] = tf32r(b4.z);
            Bs[r * APAD + c + 3] = tf32r(b4.w);
        }
        __syncthreads();

        #pragma unroll
        for (int ks = 0; ks < 4; ++ks) {
            float a[4][4];
            #pragma unroll
            for (int mt = 0; mt < 4; ++mt) {
                int rb = wm * 64 + mt * 16;
                a[mt][0] = As[(rb + g)     * APAD + ks * 8 + tig];
                a[mt][1] = As[(rb + g + 8) * APAD + ks * 8 + tig];
                a[mt][2] = As[(rb + g)     * APAD + ks * 8 + tig + 4];
                a[mt][3] = As[(rb + g + 8) * APAD + ks * 8 + tig + 4];
            }
            float b[4][2];
            #pragma unroll
            for (int nt = 0; nt < 4; ++nt) {
                int cb = wn * 32 + nt * 8 + g;
                b[nt][0] = Bs[cb * APAD + ks * 8 + tig];
                b[nt][1] = Bs[cb * APAD + ks * 8 + tig + 4];
            }
            #pragma unroll
            for (int mt = 0; mt < 4; ++mt)
                #pragma unroll
                for (int nt = 0; nt < 4; ++nt)
                    mma_tf32(acc[mt][nt], a[mt], b[nt]);
        }
        __syncthreads();
    }

    #pragma unroll
    for (int mt = 0; mt < 4; ++mt) {
        int r = row0 + wm * 64 + mt * 16 + g;
        #pragma unroll
        for (int nt = 0; nt < 4; ++nt) {
            int c = col0 + wn * 32 + nt * 8 + 2 * tig;
            *(float2*)(C + (size_t)r * Nc + c) =
                make_float2(acc[mt][nt][0], acc[mt][nt][1]);
            *(float2*)(C + (size_t)(r + 8) * Nc + c) =
                make_float2(acc[mt][nt][2], acc[mt][nt][3]);
        }
    }
}

// ---------------------------------------------------------------------------
// RoPE in-place on Q [N,H,64] and K [N,KVH,64]
// ---------------------------------------------------------------------------
__global__ __launch_bounds__(256) void rope_kernel(
    const float* __restrict__ cosT, const float* __restrict__ sinT)
{
    const int QP = NSEQ * NHEAD * 32;
    const int KP = NSEQ * KVH * 32;
    int idx = blockIdx.x * blockDim.x + threadIdx.x;
    if (idx >= QP + KP) return;

    float* base;
    int n, d;
    if (idx < QP) {
        n = idx / (NHEAD * 32);
        int rem = idx % (NHEAD * 32);
        int h = rem >> 5;
        d = rem & 31;
        base = g_Q + (size_t)n * DIM + h * HD;
    } else {
        int k = idx - QP;
        n = k / (KVH * 32);
        int rem = k % (KVH * 32);
        int h = rem >> 5;
        d = rem & 31;
        base = g_K + (size_t)n * KV_DIM + h * HD;
    }
    float c = cosT[n * HD + d];
    float s = sinT[n * HD + d];
    float x0 = base[d];
    float x1 = base[d + 32];
    base[d]      = x0 * c - x1 * s;
    base[d + 32] = x1 * c + x0 * s;
}

// ---------------------------------------------------------------------------
// Flash attention (causal, GQA) with tf32 mma for S = QK^T and O += P V.
// Block = 4 warps, tile 64 q-rows x 64 k-cols. Warp w owns q-rows 16w..16w+15.
// ---------------------------------------------------------------------------
#define AP 68   // 68 % 32 == 4 -> conflict-free fragment loads

__global__ __launch_bounds__(128) void attn_mma(float* __restrict__ Y)
{
    extern __shared__ float sm[];
    float* Qs = sm;                 // 64*AP
    float* Ks = Qs + 64 * AP;
    float* Vt = Ks + 64 * AP;       // transposed: Vt[d][s]
    float* Ps = Vt + 64 * AP;

    const int h  = blockIdx.x;
    const int q0 = blockIdx.y * 64;
    const int kh = h >> 3;          // / REP

    const int tid  = threadIdx.x;
    const int warp = tid >> 5, lane = tid & 31;
    const int g = lane >> 2, tig = lane & 3;
    const int rl0 = 16 * warp + g;  // local q-row of c0/c1 (c2/c3 at +8)

    // Load Q tile, fold softmax scale (exact power of two)
    #pragma unroll
    for (int f = tid; f < 1024; f += 128) {
        int r = f >> 4, c = (f & 15) * 4;
        float4 v = *(const float4*)(g_Q + (size_t)(q0 + r) * DIM + h * HD + c);
        Qs[r * AP + c + 0] = tf32r(v.x * SCALE);
        Qs[r * AP + c + 1] = tf32r(v.y * SCALE);
        Qs[r * AP + c + 2] = tf32r(v.z * SCALE);
        Qs[r * AP + c + 3] = tf32r(v.w * SCALE);
    }

    float O[8][4];
    #pragma unroll
    for (int nt = 0; nt < 8; ++nt)
        #pragma unroll
        for (int r = 0; r < 4; ++r) O[nt][r] = 0.f;
    float m0 = -1e30f, m1 = -1e30f, l0 = 0.f, l1 = 0.f;

    for (int k0 = 0; k0 <= q0; k0 += 64) {
        // Load K (row-major) and V (transposed) tiles
        #pragma unroll
        for (int f = tid; f < 1024; f += 128) {
            int r = f >> 4, c = (f & 15) * 4;
            float4 kv = *(const float4*)(g_K + (size_t)(k0 + r) * KV_DIM + kh * HD + c);
            float4 vv = *(const float4*)(g_V + (size_t)(k0 + r) * KV_DIM + kh * HD + c);
            Ks[r * AP + c + 0] = tf32r(kv.x);
            Ks[r * AP + c + 1] = tf32r(kv.y);
            Ks[r * AP + c + 2] = tf32r(kv.z);
            Ks[r * AP + c + 3] = tf32r(kv.w);
            Vt[(c + 0) * AP + r] = tf32r(vv.x);
            Vt[(c + 1) * AP + r] = tf32r(vv.y);
            Vt[(c + 2) * AP + r] = tf32r(vv.z);
            Vt[(c + 3) * AP + r] = tf32r(vv.w);
        }
        __syncthreads();

        // S = Q K^T  (16x64 per warp)
        float S[8][4];
        #pragma unroll
        for (int nt = 0; nt < 8; ++nt)
            #pragma unroll
            for (int r = 0; r < 4; ++r) S[nt][r] = 0.f;

        #pragma unroll
        for (int ks = 0; ks < 8; ++ks) {
            float a[4];
            a[0] = Qs[(rl0)     * AP + ks * 8 + tig];
            a[1] = Qs[(rl0 + 8) * AP + ks * 8 + tig];
            a[2] = Qs[(rl0)     * AP + ks * 8 + tig + 4];
            a[3] = Qs[(rl0 + 8) * AP + ks * 8 + tig + 4];
            #pragma unroll
            for (int nt = 0; nt < 8; ++nt) {
                float b[2];
                b[0] = Ks[(nt * 8 + g) * AP + ks * 8 + tig];
                b[1] = Ks[(nt * 8 + g) * AP + ks * 8 + tig + 4];
                mma_tf32(S[nt], a, b);
            }
        }

        // Causal mask (diagonal tile only)
        if (k0 == q0) {
            #pragma unroll
            for (int nt = 0; nt < 8; ++nt) {
                int cc = nt * 8 + 2 * tig;
                if (cc     > rl0)     S[nt][0] = -1e30f;
                if (cc + 1 > rl0)     S[nt][1] = -1e30f;
                if (cc     > rl0 + 8) S[nt][2] = -1e30f;
                if (cc + 1 > rl0 + 8) S[nt][3] = -1e30f;
            }
        }

        // Online softmax per row (rows rl0 and rl0+8), 4-lane groups via bfly
        float mx0 = -1e30f, mx1 = -1e30f;
        #pragma unroll
        for (int nt = 0; nt < 8; ++nt) {
            mx0 = fmaxf(mx0, fmaxf(S[nt][0], S[nt][1]));
            mx1 = fmaxf(mx1, fmaxf(S[nt][2], S[nt][3]));
        }
        mx0 = fmaxf(mx0, __shfl_xor_sync(0xffffffff, mx0, 1));
        mx0 = fmaxf(mx0, __shfl_xor_sync(0xffffffff, mx0, 2));
        mx1 = fmaxf(mx1, __shfl_xor_sync(0xffffffff, mx1, 1));
        mx1 = fmaxf(mx1, __shfl_xor_sync(0xffffffff, mx1, 2));

        float mn0 = fmaxf(m0, mx0), mn1 = fmaxf(m1, mx1);
        float al0 = __expf(m0 - mn0), al1 = __expf(m1 - mn1);

        float s0 = 0.f, s1 = 0.f;
        #pragma unroll
        for (int nt = 0; nt < 8; ++nt) {
            S[nt][0] = __expf(S[nt][0] - mn0);
            S[nt][1] = __expf(S[nt][1] - mn0);
            S[nt][2] = __expf(S[nt][2] - mn1);
            S[nt][3] = __expf(S[nt][3] - mn1);
            s0 += S[nt][0] + S[nt][1];
            s1 += S[nt][2] + S[nt][3];
        }
        s0 += __shfl_xor_sync(0xffffffff, s0, 1);
        s0 += __shfl_xor_sync(0xffffffff, s0, 2);
        s1 += __shfl_xor_sync(0xffffffff, s1, 1);
        s1 += __shfl_xor_sync(0xffffffff, s1, 2);

        m0 = mn0; m1 = mn1;
        l0 = l0 * al0 + s0;
        l1 = l1 * al1 + s1;

        #pragma unroll
        for (int nt = 0; nt < 8; ++nt) {
            O[nt][0] *= al0; O[nt][1] *= al0;
            O[nt][2] *= al1; O[nt][3] *= al1;
        }

        // Write P into smem (only this warp reads its own rows)
        #pragma unroll
        for (int nt = 0; nt < 8; ++nt) {
            int cc = nt * 8 + 2 * tig;
            Ps[(rl0)     * AP + cc]     = tf32r(S[nt][0]);
            Ps[(rl0)     * AP + cc + 1] = tf32r(S[nt][1]);
            Ps[(rl0 + 8) * AP + cc]     = tf32r(S[nt][2]);
            Ps[(rl0 + 8) * AP + cc + 1] = tf32r(S[nt][3]);
        }
        __syncwarp();

        // O += P V
        #pragma unroll
        for (int ks = 0; ks < 8; ++ks) {
            float a[4];
            a[0] = Ps[(rl0)     * AP + ks * 8 + tig];
            a[1] = Ps[(rl0 + 8) * AP + ks * 8 + tig];
            a[2] = Ps[(rl0)     * AP + ks * 8 + tig + 4];
            a[3] = Ps[(rl0 + 8) * AP + ks * 8 + tig + 4];
            #pragma unroll
            for (int nt = 0; nt < 8; ++nt) {
                float b[2];
                b[0] = Vt[(nt * 8 + g) * AP + ks * 8 + tig];
                b[1] = Vt[(nt * 8 + g) * AP + ks * 8 + tig + 4];
                mma_tf32(O[nt], a, b);
            }
        }
        __syncthreads();   // before next K/V tile overwrite
    }

    // Normalize + store
    float inv0 = 1.f / l0, inv1 = 1.f / l1;
    #pragma unroll
    for (int nt = 0; nt < 8; ++nt) {
        int r = q0 + rl0;
        int c = h * HD + nt * 8 + 2 * tig;
        *(float2*)(Y + (size_t)r * DIM + c) =
            make_float2(O[nt][0] * inv0, O[nt][1] * inv0);
        *(float2*)(Y + (size_t)(r + 8) * DIM + c) =
            make_float2(O[nt][2] * inv1, O[nt][3] * inv1);
    }
}

// ---------------------------------------------------------------------------
// Launch
// ---------------------------------------------------------------------------
extern "C" void kernel_launch(void* const* d_in, const int* in_sizes, int n_in,
                              void* d_out, int out_size)
{
    const float* x    = (const float*)d_in[0];
    const float* Wq   = (const float*)d_in[1];
    const float* Wk   = (const float*)d_in[2];
    const float* Wv   = (const float*)d_in[3];
    const float* Wo   = (const float*)d_in[4];
    const float* cosT = (const float*)d_in[5];
    const float* sinT = (const float*)d_in[6];
    float* out = (float*)d_out;

    float *dQ, *dK, *dV, *dY;
    cudaGetSymbolAddress((void**)&dQ, g_Q);
    cudaGetSymbolAddress((void**)&dK, g_K);
    cudaGetSymbolAddress((void**)&dV, g_V);
    cudaGetSymbolAddress((void**)&dY, g_Y);

    // QKV projections
    gemm_tf32<<<dim3(DIM / 128, NSEQ / 128), 256>>>(x, Wq, dQ, NSEQ, DIM, DIM);
    gemm_tf32<<<dim3(KV_DIM / 128, NSEQ / 128), 256>>>(x, Wk, dK, NSEQ, KV_DIM, DIM);
    gemm_tf32<<<dim3(KV_DIM / 128, NSEQ / 128), 256>>>(x, Wv, dV, NSEQ, KV_DIM, DIM);

    // RoPE
    {
        int total = NSEQ * NHEAD * 32 + NSEQ * KVH * 32;
        rope_kernel<<<(total + 255) / 256, 256>>>(cosT, sinT);
    }

    // Attention
    {
        int smem = 4 * 64 * AP * sizeof(float);  // ~69.6 KB
        cudaFuncSetAttribute(attn_mma,
                             cudaFuncAttributeMaxDynamicSharedMemorySize, smem);
        attn_mma<<<dim3(NHEAD, NSEQ / 64), 128, smem>>>(dY);
    }

    // Output projection
    gemm_tf32<<<dim3(DIM / 128, NSEQ / 128), 256>>>(dY, Wo, out, NSEQ, DIM, DIM);
}

// round 9
// speedup vs baseline: 3.2285x; 1.1839x over previous
#include <cuda_runtime.h>
#include <cuda_bf16.h>
#include <cstdint>
#include <math.h>

// Problem constants
#define NSEQ   2048
#define DIM    2048
#define NHEAD  32
#define KVH    4
#define REP    8
#define HD     64
#define KV_DIM 256
#define SCALE  0.125f

// Scratch
__device__ float g_Q[NSEQ * DIM];
__device__ float g_K[NSEQ * KV_DIM];
__device__ float g_V[NSEQ * KV_DIM];
__device__ float g_Y[NSEQ * DIM];

// Round fp32 -> tf32 (round-to-nearest) kept in a float container.
__device__ __forceinline__ float tf32r(float x) {
    unsigned int r;
    asm("cvt.rna.tf32.f32 %0, %1;" : "=r"(r) : "f"(x));
    return __uint_as_float(r);
}

// m16n8k8 tf32 mma, acc fp32
__device__ __forceinline__ void mma_tf32(float c[4], const float a[4], const float b[2]) {
    asm volatile(
        "mma.sync.aligned.m16n8k8.row.col.f32.tf32.tf32.f32 "
        "{%0,%1,%2,%3}, {%4,%5,%6,%7}, {%8,%9}, {%0,%1,%2,%3};\n"
        : "+f"(c[0]), "+f"(c[1]), "+f"(c[2]), "+f"(c[3])
        : "r"(__float_as_uint(a[0])), "r"(__float_as_uint(a[1])),
          "r"(__float_as_uint(a[2])), "r"(__float_as_uint(a[3])),
          "r"(__float_as_uint(b[0])), "r"(__float_as_uint(b[1])));
}

// ---------------------------------------------------------------------------
// GEMM: C[M,Nc] = A[M,K] * B[Nc,K]^T via tf32 mma.sync.
// Block 128x128, BK=32, 8 warps (2x4), warp tile 64x32.
// Register double-buffered mainloop: LDG for tile t+1 issued before compute
// of tile t; STS after compute. blockIdx.z selects (B0,C0) vs (B1,C1) so the
// K and V projections run in one launch.
// ---------------------------------------------------------------------------
#define BK 32
#define APAD 36   // 36 % 32 == 4 -> (4g + tig) conflict-free fragment loads

__global__ __launch_bounds__(256) void gemm_tf32(
    const float* __restrict__ A,
    const float* __restrict__ B0, const float* __restrict__ B1,
    float* __restrict__ C0, float* __restrict__ C1,
    int M, int Nc, int K)
{
    __shared__ float As[128 * APAD];
    __shared__ float Bs[128 * APAD];

    const float* __restrict__ B = blockIdx.z ? B1 : B0;
    float* __restrict__ C = blockIdx.z ? C1 : C0;

    const int tid  = threadIdx.x;
    const int warp = tid >> 5, lane = tid & 31;
    const int g = lane >> 2, tig = lane & 3;
    const int wm = warp >> 2;       // 0..1
    const int wn = warp & 3;        // 0..3
    const int row0 = blockIdx.y * 128;
    const int col0 = blockIdx.x * 128;

    float acc[4][4][4];
    #pragma unroll
    for (int mt = 0; mt < 4; ++mt)
        #pragma unroll
        for (int nt = 0; nt < 4; ++nt)
            #pragma unroll
            for (int r = 0; r < 4; ++r) acc[mt][nt][r] = 0.f;

    float4 ra[4], rb[4];

    auto ldtile = [&](int k0) {
        #pragma unroll
        for (int i = 0; i < 4; ++i) {
            int f = tid + i * 256;
            int r = f >> 3, c = (f & 7) * 4;
            ra[i] = *(const float4*)(A + (size_t)(row0 + r) * K + k0 + c);
            rb[i] = *(const float4*)(B + (size_t)(col0 + r) * K + k0 + c);
        }
    };
    auto sttile = [&]() {
        #pragma unroll
        for (int i = 0; i < 4; ++i) {
            int f = tid + i * 256;
            int r = f >> 3, c = (f & 7) * 4;
            As[r * APAD + c + 0] = tf32r(ra[i].x);
            As[r * APAD + c + 1] = tf32r(ra[i].y);
            As[r * APAD + c + 2] = tf32r(ra[i].z);
            As[r * APAD + c + 3] = tf32r(ra[i].w);
            Bs[r * APAD + c + 0] = tf32r(rb[i].x);
            Bs[r * APAD + c + 1] = tf32r(rb[i].y);
            Bs[r * APAD + c + 2] = tf32r(rb[i].z);
            Bs[r * APAD + c + 3] = tf32r(rb[i].w);
        }
    };
    auto compute = [&]() {
        #pragma unroll
        for (int ks = 0; ks < 4; ++ks) {
            float a[4][4];
            #pragma unroll
            for (int mt = 0; mt < 4; ++mt) {
                int rb_ = wm * 64 + mt * 16;
                a[mt][0] = As[(rb_ + g)     * APAD + ks * 8 + tig];
                a[mt][1] = As[(rb_ + g + 8) * APAD + ks * 8 + tig];
                a[mt][2] = As[(rb_ + g)     * APAD + ks * 8 + tig + 4];
                a[mt][3] = As[(rb_ + g + 8) * APAD + ks * 8 + tig + 4];
            }
            float b[4][2];
            #pragma unroll
            for (int nt = 0; nt < 4; ++nt) {
                int cb = wn * 32 + nt * 8 + g;
                b[nt][0] = Bs[cb * APAD + ks * 8 + tig];
                b[nt][1] = Bs[cb * APAD + ks * 8 + tig + 4];
            }
            #pragma unroll
            for (int mt = 0; mt < 4; ++mt)
                #pragma unroll
                for (int nt = 0; nt < 4; ++nt)
                    mma_tf32(acc[mt][nt], a[mt], b[nt]);
        }
    };

    // Pipelined mainloop
    ldtile(0);
    sttile();
    __syncthreads();
    for (int k0 = BK; k0 < K; k0 += BK) {
        ldtile(k0);          // LDGs for t+1 in flight during compute of t
        compute();
        __syncthreads();
        sttile();
        __syncthreads();
    }
    compute();

    #pragma unroll
    for (int mt = 0; mt < 4; ++mt) {
        int r = row0 + wm * 64 + mt * 16 + g;
        #pragma unroll
        for (int nt = 0; nt < 4; ++nt) {
            int c = col0 + wn * 32 + nt * 8 + 2 * tig;
            *(float2*)(C + (size_t)r * Nc + c) =
                make_float2(acc[mt][nt][0], acc[mt][nt][1]);
            *(float2*)(C + (size_t)(r + 8) * Nc + c) =
                make_float2(acc[mt][nt][2], acc[mt][nt][3]);
        }
    }
}

// ---------------------------------------------------------------------------
// RoPE in-place on Q [N,H,64] and K [N,KVH,64]
// ---------------------------------------------------------------------------
__global__ __launch_bounds__(256) void rope_kernel(
    const float* __restrict__ cosT, const float* __restrict__ sinT)
{
    const int QP = NSEQ * NHEAD * 32;
    const int KP = NSEQ * KVH * 32;
    int idx = blockIdx.x * blockDim.x + threadIdx.x;
    if (idx >= QP + KP) return;

    float* base;
    int n, d;
    if (idx < QP) {
        n = idx / (NHEAD * 32);
        int rem = idx % (NHEAD * 32);
        int h = rem >> 5;
        d = rem & 31;
        base = g_Q + (size_t)n * DIM + h * HD;
    } else {
        int k = idx - QP;
        n = k / (KVH * 32);
        int rem = k % (KVH * 32);
        int h = rem >> 5;
        d = rem & 31;
        base = g_K + (size_t)n * KV_DIM + h * HD;
    }
    float c = cosT[n * HD + d];
    float s = sinT[n * HD + d];
    float x0 = base[d];
    float x1 = base[d + 32];
    base[d]      = x0 * c - x1 * s;
    base[d + 32] = x1 * c + x0 * s;
}

// ---------------------------------------------------------------------------
// Flash attention (causal, GQA) with tf32 mma for S = QK^T and O += P V.
// Block = 4 warps, tile 64 q-rows x 64 k-cols. Warp w owns q-rows 16w..16w+15.
// q-tile index reversed so the heaviest blocks launch first (causal balance).
// ---------------------------------------------------------------------------
#define AP 68   // 68 % 32 == 4 -> conflict-free fragment loads

__global__ __launch_bounds__(128) void attn_mma(float* __restrict__ Y)
{
    extern __shared__ float sm[];
    float* Qs = sm;                 // 64*AP
    float* Ks = Qs + 64 * AP;
    float* Vt = Ks + 64 * AP;       // transposed: Vt[d][s]
    float* Ps = Vt + 64 * AP;

    const int h  = blockIdx.x;
    const int q0 = (gridDim.y - 1 - blockIdx.y) * 64;   // heavy tiles first
    const int kh = h >> 3;          // / REP

    const int tid  = threadIdx.x;
    const int warp = tid >> 5, lane = tid & 31;
    const int g = lane >> 2, tig = lane & 3;
    const int rl0 = 16 * warp + g;  // local q-row of c0/c1 (c2/c3 at +8)

    // Load Q tile, fold softmax scale (exact power of two)
    #pragma unroll
    for (int f = tid; f < 1024; f += 128) {
        int r = f >> 4, c = (f & 15) * 4;
        float4 v = *(const float4*)(g_Q + (size_t)(q0 + r) * DIM + h * HD + c);
        Qs[r * AP + c + 0] = tf32r(v.x * SCALE);
        Qs[r * AP + c + 1] = tf32r(v.y * SCALE);
        Qs[r * AP + c + 2] = tf32r(v.z * SCALE);
        Qs[r * AP + c + 3] = tf32r(v.w * SCALE);
    }

    float O[8][4];
    #pragma unroll
    for (int nt = 0; nt < 8; ++nt)
        #pragma unroll
        for (int r = 0; r < 4; ++r) O[nt][r] = 0.f;
    float m0 = -1e30f, m1 = -1e30f, l0 = 0.f, l1 = 0.f;

    for (int k0 = 0; k0 <= q0; k0 += 64) {
        // Load K (row-major) and V (transposed) tiles
        #pragma unroll
        for (int f = tid; f < 1024; f += 128) {
            int r = f >> 4, c = (f & 15) * 4;
            float4 kv = *(const float4*)(g_K + (size_t)(k0 + r) * KV_DIM + kh * HD + c);
            float4 vv = *(const float4*)(g_V + (size_t)(k0 + r) * KV_DIM + kh * HD + c);
            Ks[r * AP + c + 0] = tf32r(kv.x);
            Ks[r * AP + c + 1] = tf32r(kv.y);
            Ks[r * AP + c + 2] = tf32r(kv.z);
            Ks[r * AP + c + 3] = tf32r(kv.w);
            Vt[(c + 0) * AP + r] = tf32r(vv.x);
            Vt[(c + 1) * AP + r] = tf32r(vv.y);
            Vt[(c + 2) * AP + r] = tf32r(vv.z);
            Vt[(c + 3) * AP + r] = tf32r(vv.w);
        }
        __syncthreads();

        // S = Q K^T  (16x64 per warp)
        float S[8][4];
        #pragma unroll
        for (int nt = 0; nt < 8; ++nt)
            #pragma unroll
            for (int r = 0; r < 4; ++r) S[nt][r] = 0.f;

        #pragma unroll
        for (int ks = 0; ks < 8; ++ks) {
            float a[4];
            a[0] = Qs[(rl0)     * AP + ks * 8 + tig];
            a[1] = Qs[(rl0 + 8) * AP + ks * 8 + tig];
            a[2] = Qs[(rl0)     * AP + ks * 8 + tig + 4];
            a[3] = Qs[(rl0 + 8) * AP + ks * 8 + tig + 4];
            #pragma unroll
            for (int nt = 0; nt < 8; ++nt) {
                float b[2];
                b[0] = Ks[(nt * 8 + g) * AP + ks * 8 + tig];
                b[1] = Ks[(nt * 8 + g) * AP + ks * 8 + tig + 4];
                mma_tf32(S[nt], a, b);
            }
        }

        // Causal mask (diagonal tile only)
        if (k0 == q0) {
            #pragma unroll
            for (int nt = 0; nt < 8; ++nt) {
                int cc = nt * 8 + 2 * tig;
                if (cc     > rl0)     S[nt][0] = -1e30f;
                if (cc + 1 > rl0)     S[nt][1] = -1e30f;
                if (cc     > rl0 + 8) S[nt][2] = -1e30f;
                if (cc + 1 > rl0 + 8) S[nt][3] = -1e30f;
            }
        }

        // Online softmax per row (rows rl0 and rl0+8), 4-lane groups via bfly
        float mx0 = -1e30f, mx1 = -1e30f;
        #pragma unroll
        for (int nt = 0; nt < 8; ++nt) {
            mx0 = fmaxf(mx0, fmaxf(S[nt][0], S[nt][1]));
            mx1 = fmaxf(mx1, fmaxf(S[nt][2], S[nt][3]));
        }
        mx0 = fmaxf(mx0, __shfl_xor_sync(0xffffffff, mx0, 1));
        mx0 = fmaxf(mx0, __shfl_xor_sync(0xffffffff, mx0, 2));
        mx1 = fmaxf(mx1, __shfl_xor_sync(0xffffffff, mx1, 1));
        mx1 = fmaxf(mx1, __shfl_xor_sync(0xffffffff, mx1, 2));

        float mn0 = fmaxf(m0, mx0), mn1 = fmaxf(m1, mx1);
        float al0 = __expf(m0 - mn0), al1 = __expf(m1 - mn1);

        float s0 = 0.f, s1 = 0.f;
        #pragma unroll
        for (int nt = 0; nt < 8; ++nt) {
            S[nt][0] = __expf(S[nt][0] - mn0);
            S[nt][1] = __expf(S[nt][1] - mn0);
            S[nt][2] = __expf(S[nt][2] - mn1);
            S[nt][3] = __expf(S[nt][3] - mn1);
            s0 += S[nt][0] + S[nt][1];
            s1 += S[nt][2] + S[nt][3];
        }
        s0 += __shfl_xor_sync(0xffffffff, s0, 1);
        s0 += __shfl_xor_sync(0xffffffff, s0, 2);
        s1 += __shfl_xor_sync(0xffffffff, s1, 1);
        s1 += __shfl_xor_sync(0xffffffff, s1, 2);

        m0 = mn0; m1 = mn1;
        l0 = l0 * al0 + s0;
        l1 = l1 * al1 + s1;

        #pragma unroll
        for (int nt = 0; nt < 8; ++nt) {
            O[nt][0] *= al0; O[nt][1] *= al0;
            O[nt][2] *= al1; O[nt][3] *= al1;
        }

        // Write P into smem (only this warp reads its own rows)
        #pragma unroll
        for (int nt = 0; nt < 8; ++nt) {
            int cc = nt * 8 + 2 * tig;
            Ps[(rl0)     * AP + cc]     = tf32r(S[nt][0]);
            Ps[(rl0)     * AP + cc + 1] = tf32r(S[nt][1]);
            Ps[(rl0 + 8) * AP + cc]     = tf32r(S[nt][2]);
            Ps[(rl0 + 8) * AP + cc + 1] = tf32r(S[nt][3]);
        }
        __syncwarp();

        // O += P V
        #pragma unroll
        for (int ks = 0; ks < 8; ++ks) {
            float a[4];
            a[0] = Ps[(rl0)     * AP + ks * 8 + tig];
            a[1] = Ps[(rl0 + 8) * AP + ks * 8 + tig];
            a[2] = Ps[(rl0)     * AP + ks * 8 + tig + 4];
            a[3] = Ps[(rl0 + 8) * AP + ks * 8 + tig + 4];
            #pragma unroll
            for (int nt = 0; nt < 8; ++nt) {
                float b[2];
                b[0] = Vt[(nt * 8 + g) * AP + ks * 8 + tig];
                b[1] = Vt[(nt * 8 + g) * AP + ks * 8 + tig + 4];
                mma_tf32(O[nt], a, b);
            }
        }
        __syncthreads();   // before next K/V tile overwrite
    }

    // Normalize + store
    float inv0 = 1.f / l0, inv1 = 1.f / l1;
    #pragma unroll
    for (int nt = 0; nt < 8; ++nt) {
        int r = q0 + rl0;
        int c = h * HD + nt * 8 + 2 * tig;
        *(float2*)(Y + (size_t)r * DIM + c) =
            make_float2(O[nt][0] * inv0, O[nt][1] * inv0);
        *(float2*)(Y + (size_t)(r + 8) * DIM + c) =
            make_float2(O[nt][2] * inv1, O[nt][3] * inv1);
    }
}

// ---------------------------------------------------------------------------
// Launch
// ---------------------------------------------------------------------------
extern "C" void kernel_launch(void* const* d_in, const int* in_sizes, int n_in,
                              void* d_out, int out_size)
{
    const float* x    = (const float*)d_in[0];
    const float* Wq   = (const float*)d_in[1];
    const float* Wk   = (const float*)d_in[2];
    const float* Wv   = (const float*)d_in[3];
    const float* Wo   = (const float*)d_in[4];
    const float* cosT = (const float*)d_in[5];
    const float* sinT = (const float*)d_in[6];
    float* out = (float*)d_out;

    float *dQ, *dK, *dV, *dY;
    cudaGetSymbolAddress((void**)&dQ, g_Q);
    cudaGetSymbolAddress((void**)&dK, g_K);
    cudaGetSymbolAddress((void**)&dV, g_V);
    cudaGetSymbolAddress((void**)&dY, g_Y);

    // Q projection
    gemm_tf32<<<dim3(DIM / 128, NSEQ / 128, 1), 256>>>(
        x, Wq, Wq, dQ, dQ, NSEQ, DIM, DIM);
    // K and V projections fused in one launch (blockIdx.z selects)
    gemm_tf32<<<dim3(KV_DIM / 128, NSEQ / 128, 2), 256>>>(
        x, Wk, Wv, dK, dV, NSEQ, KV_DIM, DIM);

    // RoPE
    {
        int total = NSEQ * NHEAD * 32 + NSEQ * KVH * 32;
        rope_kernel<<<(total + 255) / 256, 256>>>(cosT, sinT);
    }

    // Attention
    {
        int smem = 4 * 64 * AP * sizeof(float);  // ~69.6 KB
        cudaFuncSetAttribute(attn_mma,
                             cudaFuncAttributeMaxDynamicSharedMemorySize, smem);
        attn_mma<<<dim3(NHEAD, NSEQ / 64), 128, smem>>>(dY);
    }

    // Output projection
    gemm_tf32<<<dim3(DIM / 128, NSEQ / 128, 1), 256>>>(
        dY, Wo, Wo, out, out, NSEQ, DIM, DIM);
}

// round 11
// speedup vs baseline: 3.3626x; 1.0415x over previous
#include <cuda_runtime.h>
#include <cuda_bf16.h>
#include <cstdint>
#include <math.h>

// Problem constants
#define NSEQ   2048
#define DIM    2048
#define NHEAD  32
#define KVH    4
#define REP    8
#define HD     64
#define KV_DIM 256
#define SCALE  0.125f

// Scratch
__device__ float g_Q[NSEQ * DIM];
__device__ float g_K[NSEQ * KV_DIM];
__device__ float g_V[NSEQ * KV_DIM];
__device__ float g_Y[NSEQ * DIM];

// Round fp32 -> tf32 (round-to-nearest) kept in a float container.
__device__ __forceinline__ float tf32r(float x) {
    unsigned int r;
    asm("cvt.rna.tf32.f32 %0, %1;" : "=r"(r) : "f"(x));
    return __uint_as_float(r);
}

// m16n8k8 tf32 mma, acc fp32
__device__ __forceinline__ void mma_tf32(float c[4], const float a[4], const float b[2]) {
    asm volatile(
        "mma.sync.aligned.m16n8k8.row.col.f32.tf32.tf32.f32 "
        "{%0,%1,%2,%3}, {%4,%5,%6,%7}, {%8,%9}, {%0,%1,%2,%3};\n"
        : "+f"(c[0]), "+f"(c[1]), "+f"(c[2]), "+f"(c[3])
        : "r"(__float_as_uint(a[0])), "r"(__float_as_uint(a[1])),
          "r"(__float_as_uint(a[2])), "r"(__float_as_uint(a[3])),
          "r"(__float_as_uint(b[0])), "r"(__float_as_uint(b[1])));
}

// ---------------------------------------------------------------------------
// GEMM: C[M,Nc] = A[M,K] * B[Nc,K]^T via tf32 mma.sync. (unchanged from R9)
// ---------------------------------------------------------------------------
#define BK 32
#define APAD 36

__global__ __launch_bounds__(256) void gemm_tf32(
    const float* __restrict__ A,
    const float* __restrict__ B0, const float* __restrict__ B1,
    float* __restrict__ C0, float* __restrict__ C1,
    int M, int Nc, int K)
{
    __shared__ float As[128 * APAD];
    __shared__ float Bs[128 * APAD];

    const float* __restrict__ B = blockIdx.z ? B1 : B0;
    float* __restrict__ C = blockIdx.z ? C1 : C0;

    const int tid  = threadIdx.x;
    const int warp = tid >> 5, lane = tid & 31;
    const int g = lane >> 2, tig = lane & 3;
    const int wm = warp >> 2;
    const int wn = warp & 3;
    const int row0 = blockIdx.y * 128;
    const int col0 = blockIdx.x * 128;

    float acc[4][4][4];
    #pragma unroll
    for (int mt = 0; mt < 4; ++mt)
        #pragma unroll
        for (int nt = 0; nt < 4; ++nt)
            #pragma unroll
            for (int r = 0; r < 4; ++r) acc[mt][nt][r] = 0.f;

    float4 ra[4], rb[4];

    auto ldtile = [&](int k0) {
        #pragma unroll
        for (int i = 0; i < 4; ++i) {
            int f = tid + i * 256;
            int r = f >> 3, c = (f & 7) * 4;
            ra[i] = *(const float4*)(A + (size_t)(row0 + r) * K + k0 + c);
            rb[i] = *(const float4*)(B + (size_t)(col0 + r) * K + k0 + c);
        }
    };
    auto sttile = [&]() {
        #pragma unroll
        for (int i = 0; i < 4; ++i) {
            int f = tid + i * 256;
            int r = f >> 3, c = (f & 7) * 4;
            As[r * APAD + c + 0] = tf32r(ra[i].x);
            As[r * APAD + c + 1] = tf32r(ra[i].y);
            As[r * APAD + c + 2] = tf32r(ra[i].z);
            As[r * APAD + c + 3] = tf32r(ra[i].w);
            Bs[r * APAD + c + 0] = tf32r(rb[i].x);
            Bs[r * APAD + c + 1] = tf32r(rb[i].y);
            Bs[r * APAD + c + 2] = tf32r(rb[i].z);
            Bs[r * APAD + c + 3] = tf32r(rb[i].w);
        }
    };
    auto compute = [&]() {
        #pragma unroll
        for (int ks = 0; ks < 4; ++ks) {
            float a[4][4];
            #pragma unroll
            for (int mt = 0; mt < 4; ++mt) {
                int rb_ = wm * 64 + mt * 16;
                a[mt][0] = As[(rb_ + g)     * APAD + ks * 8 + tig];
                a[mt][1] = As[(rb_ + g + 8) * APAD + ks * 8 + tig];
                a[mt][2] = As[(rb_ + g)     * APAD + ks * 8 + tig + 4];
                a[mt][3] = As[(rb_ + g + 8) * APAD + ks * 8 + tig + 4];
            }
            float b[4][2];
            #pragma unroll
            for (int nt = 0; nt < 4; ++nt) {
                int cb = wn * 32 + nt * 8 + g;
                b[nt][0] = Bs[cb * APAD + ks * 8 + tig];
                b[nt][1] = Bs[cb * APAD + ks * 8 + tig + 4];
            }
            #pragma unroll
            for (int mt = 0; mt < 4; ++mt)
                #pragma unroll
                for (int nt = 0; nt < 4; ++nt)
                    mma_tf32(acc[mt][nt], a[mt], b[nt]);
        }
    };

    ldtile(0);
    sttile();
    __syncthreads();
    for (int k0 = BK; k0 < K; k0 += BK) {
        ldtile(k0);
        compute();
        __syncthreads();
        sttile();
        __syncthreads();
    }
    compute();

    #pragma unroll
    for (int mt = 0; mt < 4; ++mt) {
        int r = row0 + wm * 64 + mt * 16 + g;
        #pragma unroll
        for (int nt = 0; nt < 4; ++nt) {
            int c = col0 + wn * 32 + nt * 8 + 2 * tig;
            *(float2*)(C + (size_t)r * Nc + c) =
                make_float2(acc[mt][nt][0], acc[mt][nt][1]);
            *(float2*)(C + (size_t)(r + 8) * Nc + c) =
                make_float2(acc[mt][nt][2], acc[mt][nt][3]);
        }
    }
}

// ---------------------------------------------------------------------------
// RoPE in-place on Q [N,H,64] and K [N,KVH,64]
// ---------------------------------------------------------------------------
__global__ __launch_bounds__(256) void rope_kernel(
    const float* __restrict__ cosT, const float* __restrict__ sinT)
{
    const int QP = NSEQ * NHEAD * 32;
    const int KP = NSEQ * KVH * 32;
    int idx = blockIdx.x * blockDim.x + threadIdx.x;
    if (idx >= QP + KP) return;

    float* base;
    int n, d;
    if (idx < QP) {
        n = idx / (NHEAD * 32);
        int rem = idx % (NHEAD * 32);
        int h = rem >> 5;
        d = rem & 31;
        base = g_Q + (size_t)n * DIM + h * HD;
    } else {
        int k = idx - QP;
        n = k / (KVH * 32);
        int rem = k % (KVH * 32);
        int h = rem >> 5;
        d = rem & 31;
        base = g_K + (size_t)n * KV_DIM + h * HD;
    }
    float c = cosT[n * HD + d];
    float s = sinT[n * HD + d];
    float x0 = base[d];
    float x1 = base[d + 32];
    base[d]      = x0 * c - x1 * s;
    base[d + 32] = x1 * c + x0 * s;
}

// ---------------------------------------------------------------------------
// Flash attention (causal, GQA), tf32 mma.
// Block = 4 warps, 128 q-rows (warp owns 32 rows as two m16 fragments).
// KV tile = 64. P never touches smem: C-frag -> A-frag via shfl repack.
// ---------------------------------------------------------------------------
#define AP 68       // 68 % 32 == 4 -> conflict-free fragment loads
#define QROWS 128

__global__ __launch_bounds__(128) void attn_mma(float* __restrict__ Y)
{
    extern __shared__ float sm[];
    float* Qs = sm;                    // 128*AP
    float* Ks = Qs + QROWS * AP;       // 64*AP
    float* Vt = Ks + 64 * AP;          // 64*AP (transposed: Vt[d][s])

    const int h  = blockIdx.x;
    const int q0 = (gridDim.y - 1 - blockIdx.y) * QROWS;  // heavy tiles first
    const int kh = h >> 3;

    const int tid  = threadIdx.x;
    const int warp = tid >> 5, lane = tid & 31;
    const int g = lane >> 2, tig = lane & 3;
    const bool odd = tig & 1;
    const int src_lo = (lane & ~3) | (tig >> 1);   // repack shuffle sources
    const int src_hi = src_lo + 2;

    // Load Q tile (128 rows), fold softmax scale
    #pragma unroll
    for (int f = tid; f < QROWS * 16; f += 128) {
        int r = f >> 4, c = (f & 15) * 4;
        float4 v = *(const float4*)(g_Q + (size_t)(q0 + r) * DIM + h * HD + c);
        Qs[r * AP + c + 0] = tf32r(v.x * SCALE);
        Qs[r * AP + c + 1] = tf32r(v.y * SCALE);
        Qs[r * AP + c + 2] = tf32r(v.z * SCALE);
        Qs[r * AP + c + 3] = tf32r(v.w * SCALE);
    }

    float O[2][8][4];
    #pragma unroll
    for (int mt = 0; mt < 2; ++mt)
        #pragma unroll
        for (int nt = 0; nt < 8; ++nt)
            #pragma unroll
            for (int r = 0; r < 4; ++r) O[mt][nt][r] = 0.f;
    float m[2][2] = {{-1e30f, -1e30f}, {-1e30f, -1e30f}};
    float l[2][2] = {{0.f, 0.f}, {0.f, 0.f}};

    const int ntiles = q0 / 64 + 2;   // covers kv in [0, q0+128)
    for (int t = 0; t < ntiles; ++t) {
        const int k0 = t * 64;
        __syncthreads();   // previous tile's reads done (also Q stores at t=0)
        #pragma unroll
        for (int f = tid; f < 64 * 16; f += 128) {
            int r = f >> 4, c = (f & 15) * 4;
            float4 kv = *(const float4*)(g_K + (size_t)(k0 + r) * KV_DIM + kh * HD + c);
            float4 vv = *(const float4*)(g_V + (size_t)(k0 + r) * KV_DIM + kh * HD + c);
            Ks[r * AP + c + 0] = tf32r(kv.x);
            Ks[r * AP + c + 1] = tf32r(kv.y);
            Ks[r * AP + c + 2] = tf32r(kv.z);
            Ks[r * AP + c + 3] = tf32r(kv.w);
            Vt[(c + 0) * AP + r] = tf32r(vv.x);
            Vt[(c + 1) * AP + r] = tf32r(vv.y);
            Vt[(c + 2) * AP + r] = tf32r(vv.z);
            Vt[(c + 3) * AP + r] = tf32r(vv.w);
        }
        __syncthreads();

        #pragma unroll
        for (int mt = 0; mt < 2; ++mt) {
            const int rbase = 32 * warp + 16 * mt;  // local q-row base of frag
            const int rl = rbase + g;

            // ---- S = Q K^T (16x64) ----
            float S[8][4];
            #pragma unroll
            for (int nt = 0; nt < 8; ++nt)
                #pragma unroll
                for (int r = 0; r < 4; ++r) S[nt][r] = 0.f;

            #pragma unroll
            for (int ks = 0; ks < 8; ++ks) {
                float a[4];
                a[0] = Qs[(rbase + g)     * AP + ks * 8 + tig];
                a[1] = Qs[(rbase + g + 8) * AP + ks * 8 + tig];
                a[2] = Qs[(rbase + g)     * AP + ks * 8 + tig + 4];
                a[3] = Qs[(rbase + g + 8) * AP + ks * 8 + tig + 4];
                #pragma unroll
                for (int nt = 0; nt < 8; ++nt) {
                    float b[2];
                    b[0] = Ks[(nt * 8 + g) * AP + ks * 8 + tig];
                    b[1] = Ks[(nt * 8 + g) * AP + ks * 8 + tig + 4];
                    mma_tf32(S[nt], a, b);
                }
            }

            // ---- causal mask (only tiles crossing the diagonal) ----
            if (k0 + 63 > q0 + rbase) {
                const int row0_ = q0 + rl, row1_ = row0_ + 8;
                #pragma unroll
                for (int nt = 0; nt < 8; ++nt) {
                    int cc = k0 + nt * 8 + 2 * tig;
                    if (cc     > row0_) S[nt][0] = -1e30f;
                    if (cc + 1 > row0_) S[nt][1] = -1e30f;
                    if (cc     > row1_) S[nt][2] = -1e30f;
                    if (cc + 1 > row1_) S[nt][3] = -1e30f;
                }
            }

            // ---- online softmax (rows rl and rl+8) ----
            float mx0 = -1e30f, mx1 = -1e30f;
            #pragma unroll
            for (int nt = 0; nt < 8; ++nt) {
                mx0 = fmaxf(mx0, fmaxf(S[nt][0], S[nt][1]));
                mx1 = fmaxf(mx1, fmaxf(S[nt][2], S[nt][3]));
            }
            mx0 = fmaxf(mx0, __shfl_xor_sync(0xffffffff, mx0, 1));
            mx0 = fmaxf(mx0, __shfl_xor_sync(0xffffffff, mx0, 2));
            mx1 = fmaxf(mx1, __shfl_xor_sync(0xffffffff, mx1, 1));
            mx1 = fmaxf(mx1, __shfl_xor_sync(0xffffffff, mx1, 2));

            float mn0 = fmaxf(m[mt][0], mx0), mn1 = fmaxf(m[mt][1], mx1);
            float al0 = __expf(m[mt][0] - mn0), al1 = __expf(m[mt][1] - mn1);

            float s0 = 0.f, s1 = 0.f;
            #pragma unroll
            for (int nt = 0; nt < 8; ++nt) {
                S[nt][0] = tf32r(__expf(S[nt][0] - mn0));
                S[nt][1] = tf32r(__expf(S[nt][1] - mn0));
                S[nt][2] = tf32r(__expf(S[nt][2] - mn1));
                S[nt][3] = tf32r(__expf(S[nt][3] - mn1));
                s0 += S[nt][0] + S[nt][1];
                s1 += S[nt][2] + S[nt][3];
            }
            s0 += __shfl_xor_sync(0xffffffff, s0, 1);
            s0 += __shfl_xor_sync(0xffffffff, s0, 2);
            s1 += __shfl_xor_sync(0xffffffff, s1, 1);
            s1 += __shfl_xor_sync(0xffffffff, s1, 2);

            m[mt][0] = mn0; m[mt][1] = mn1;
            l[mt][0] = l[mt][0] * al0 + s0;
            l[mt][1] = l[mt][1] * al1 + s1;

            #pragma unroll
            for (int nt = 0; nt < 8; ++nt) {
                O[mt][nt][0] *= al0; O[mt][nt][1] *= al0;
                O[mt][nt][2] *= al1; O[mt][nt][3] *= al1;
            }

            // ---- O += P V : repack C-frag -> A-frag via shfl, no smem ----
            #pragma unroll
            for (int ks = 0; ks < 8; ++ks) {
                float x0 = __shfl_sync(0xffffffff, S[ks][0], src_lo);
                float x1 = __shfl_sync(0xffffffff, S[ks][1], src_lo);
                float y0 = __shfl_sync(0xffffffff, S[ks][2], src_lo);
                float y1 = __shfl_sync(0xffffffff, S[ks][3], src_lo);
                float z0 = __shfl_sync(0xffffffff, S[ks][0], src_hi);
                float z1 = __shfl_sync(0xffffffff, S[ks][1], src_hi);
                float w0 = __shfl_sync(0xffffffff, S[ks][2], src_hi);
                float w1 = __shfl_sync(0xffffffff, S[ks][3], src_hi);
                float pa[4];
                pa[0] = odd ? x1 : x0;   // P(row g,   col ks*8+tig)
                pa[1] = odd ? y1 : y0;   // P(row g+8, col ks*8+tig)
                pa[2] = odd ? z1 : z0;   // P(row g,   col ks*8+tig+4)
                pa[3] = odd ? w1 : w0;   // P(row g+8, col ks*8+tig+4)
                #pragma unroll
                for (int nt = 0; nt < 8; ++nt) {
                    float b[2];
                    b[0] = Vt[(nt * 8 + g) * AP + ks * 8 + tig];
                    b[1] = Vt[(nt * 8 + g) * AP + ks * 8 + tig + 4];
                    mma_tf32(O[mt][nt], pa, b);
                }
            }
        }
    }

    // Normalize + store
    #pragma unroll
    for (int mt = 0; mt < 2; ++mt) {
        const int r = q0 + 32 * warp + 16 * mt + g;
        float inv0 = 1.f / l[mt][0], inv1 = 1.f / l[mt][1];
        #pragma unroll
        for (int nt = 0; nt < 8; ++nt) {
            int c = h * HD + nt * 8 + 2 * tig;
            *(float2*)(Y + (size_t)r * DIM + c) =
                make_float2(O[mt][nt][0] * inv0, O[mt][nt][1] * inv0);
            *(float2*)(Y + (size_t)(r + 8) * DIM + c) =
                make_float2(O[mt][nt][2] * inv1, O[mt][nt][3] * inv1);
        }
    }
}

// ---------------------------------------------------------------------------
// Launch
// ---------------------------------------------------------------------------
extern "C" void kernel_launch(void* const* d_in, const int* in_sizes, int n_in,
                              void* d_out, int out_size)
{
    const float* x    = (const float*)d_in[0];
    const float* Wq   = (const float*)d_in[1];
    const float* Wk   = (const float*)d_in[2];
    const float* Wv   = (const float*)d_in[3];
    const float* Wo   = (const float*)d_in[4];
    const float* cosT = (const float*)d_in[5];
    const float* sinT = (const float*)d_in[6];
    float* out = (float*)d_out;

    float *dQ, *dK, *dV, *dY;
    cudaGetSymbolAddress((void**)&dQ, g_Q);
    cudaGetSymbolAddress((void**)&dK, g_K);
    cudaGetSymbolAddress((void**)&dV, g_V);
    cudaGetSymbolAddress((void**)&dY, g_Y);

    // Q projection
    gemm_tf32<<<dim3(DIM / 128, NSEQ / 128, 1), 256>>>(
        x, Wq, Wq, dQ, dQ, NSEQ, DIM, DIM);
    // K and V projections fused in one launch
    gemm_tf32<<<dim3(KV_DIM / 128, NSEQ / 128, 2), 256>>>(
        x, Wk, Wv, dK, dV, NSEQ, KV_DIM, DIM);

    // RoPE
    {
        int total = NSEQ * NHEAD * 32 + NSEQ * KVH * 32;
        rope_kernel<<<(total + 255) / 256, 256>>>(cosT, sinT);
    }

    // Attention
    {
        int smem = (QROWS + 64 + 64) * AP * sizeof(float);  // ~68 KB
        cudaFuncSetAttribute(attn_mma,
                             cudaFuncAttributeMaxDynamicSharedMemorySize, smem);
        attn_mma<<<dim3(NHEAD, NSEQ / QROWS), 128, smem>>>(dY);
    }

    // Output projection
    gemm_tf32<<<dim3(DIM / 128, NSEQ / 128, 1), 256>>>(
        dY, Wo, Wo, out, out, NSEQ, DIM, DIM);
}